// round 1
// baseline (speedup 1.0000x reference)
#include <cuda_runtime.h>

// Problem constants
#define Bn 16384
#define Fn 512
#define Pn 128
#define Cn 10

// Tiling
#define BM 128      // rows per block
#define KT 16       // K tile
#define TM 8
#define TN 8
#define NT 256      // threads per block
#define SROW 129    // padded si row stride (conflict-free scan reads)

__global__ __launch_bounds__(NT, 1)
void ds_kernel(const float* __restrict__ x, const float* __restrict__ w,
               const float* __restrict__ eta, const float* __restrict__ xi,
               const float* __restrict__ beta, float* __restrict__ out)
{
    extern __shared__ float sm[];
    float* xs  = sm;                       // [2][KT][BM]  x tile, transposed
    float* wsm = xs + 2 * KT * BM;         // [2][KT][BM]  w tile, transposed
    float* sit = wsm + 2 * KT * BM;        // [BM][SROW]   si values
    float* xsq = sit + BM * SROW;          // [BM]   ||x_row||^2
    float* wsq = xsq + BM;                 // [Pn]   ||w_p||^2
    float* u_s = wsq + Pn;                 // [Cn][Pn]
    float* alp = u_s + Cn * Pn;            // [Pn]
    float* gam = alp + Pn;                 // [Pn]

    const int tid  = threadIdx.x;
    const int row0 = blockIdx.x * BM;

    // ---- per-prototype tables: gamma, alpha, u[c][p]; zero the sumsq slots ----
    if (tid < Pn) {
        const int p = tid;
        float e = eta[p];
        gam[p] = e * e;
        alp[p] = 1.0f / (1.0f + __expf(-xi[p]));
        float b2[Cn];
        float bs = 0.0f;
        #pragma unroll
        for (int c = 0; c < Cn; c++) {
            float bv = beta[c * Pn + p];
            b2[c] = bv * bv;
            bs += b2[c];
        }
        float invb = 1.0f / bs;
        #pragma unroll
        for (int c = 0; c < Cn; c++) u_s[c * Pn + p] = b2[c] * invb;
        xsq[p] = 0.0f;
        wsq[p] = 0.0f;
    }

    // ---- GEMM: acc[i][j] = x_row . w_col over K=512 ----
    // Load mapping: 512 float4 per tile (128 rows x 4), 2 per thread.
    const int r0 = tid >> 2;           // row/col 0..63
    const int r1 = r0 + 64;            // row/col 64..127
    const int q0 = tid & 3;            // which float4 within KT=16

    float sx0 = 0.f, sx1 = 0.f, sw0 = 0.f, sw1 = 0.f;
    float4 vx0, vx1, vw0, vw1;

    const float4* xg = (const float4*)x;   // pitch Fn/4 = 128 float4 per row
    const float4* wg = (const float4*)w;

#define LOADT(t)                                                                \
    do {                                                                        \
        vx0 = xg[(size_t)(row0 + r0) * (Fn / 4) + (t) * 4 + q0];                \
        vx1 = xg[(size_t)(row0 + r1) * (Fn / 4) + (t) * 4 + q0];                \
        vw0 = wg[(size_t)r0 * (Fn / 4) + (t) * 4 + q0];                         \
        vw1 = wg[(size_t)r1 * (Fn / 4) + (t) * 4 + q0];                         \
    } while (0)

#define STASH(bufv)                                                             \
    do {                                                                        \
        float* xb = xs + (bufv) * KT * BM;                                      \
        float* wb = wsm + (bufv) * KT * BM;                                     \
        const int kb = q0 * 4;                                                  \
        xb[(kb + 0) * BM + r0] = vx0.x; xb[(kb + 1) * BM + r0] = vx0.y;         \
        xb[(kb + 2) * BM + r0] = vx0.z; xb[(kb + 3) * BM + r0] = vx0.w;         \
        xb[(kb + 0) * BM + r1] = vx1.x; xb[(kb + 1) * BM + r1] = vx1.y;         \
        xb[(kb + 2) * BM + r1] = vx1.z; xb[(kb + 3) * BM + r1] = vx1.w;         \
        wb[(kb + 0) * BM + r0] = vw0.x; wb[(kb + 1) * BM + r0] = vw0.y;         \
        wb[(kb + 2) * BM + r0] = vw0.z; wb[(kb + 3) * BM + r0] = vw0.w;         \
        wb[(kb + 0) * BM + r1] = vw1.x; wb[(kb + 1) * BM + r1] = vw1.y;         \
        wb[(kb + 2) * BM + r1] = vw1.z; wb[(kb + 3) * BM + r1] = vw1.w;         \
        sx0 += vx0.x*vx0.x + vx0.y*vx0.y + vx0.z*vx0.z + vx0.w*vx0.w;           \
        sx1 += vx1.x*vx1.x + vx1.y*vx1.y + vx1.z*vx1.z + vx1.w*vx1.w;           \
        sw0 += vw0.x*vw0.x + vw0.y*vw0.y + vw0.z*vw0.z + vw0.w*vw0.w;           \
        sw1 += vw1.x*vw1.x + vw1.y*vw1.y + vw1.z*vw1.z + vw1.w*vw1.w;           \
    } while (0)

    LOADT(0);
    STASH(0);
    __syncthreads();

    float acc[TM][TN];
    #pragma unroll
    for (int i = 0; i < TM; i++)
        #pragma unroll
        for (int j = 0; j < TN; j++) acc[i][j] = 0.0f;

    const int ty = tid >> 4;           // 0..15
    const int tx = tid & 15;           // 0..15
    const int ra = ty * TM;            // output row base (within tile)
    const int ca = tx * TN;            // output col base (prototype)

    const int NTILE = Fn / KT;         // 32
    for (int t = 0; t < NTILE; t++) {
        const int buf = t & 1;
        const bool more = (t + 1 < NTILE);
        if (more) LOADT(t + 1);

        const float* xb = xs + buf * KT * BM;
        const float* wb = wsm + buf * KT * BM;
        #pragma unroll
        for (int k = 0; k < KT; k++) {
            float av[TM], bv[TN];
            *(float4*)&av[0] = *(const float4*)&xb[k * BM + ra];
            *(float4*)&av[4] = *(const float4*)&xb[k * BM + ra + 4];
            *(float4*)&bv[0] = *(const float4*)&wb[k * BM + ca];
            *(float4*)&bv[4] = *(const float4*)&wb[k * BM + ca + 4];
            #pragma unroll
            for (int i = 0; i < TM; i++)
                #pragma unroll
                for (int j = 0; j < TN; j++)
                    acc[i][j] = fmaf(av[i], bv[j], acc[i][j]);
        }
        if (more) STASH(buf ^ 1);
        __syncthreads();
    }

    // ---- finalize sum-of-squares ----
    atomicAdd(&xsq[r0], sx0);
    atomicAdd(&xsq[r1], sx1);
    atomicAdd(&wsq[r0], sw0);
    atomicAdd(&wsq[r1], sw1);
    __syncthreads();

    // ---- epilogue: si = alpha * exp(-gamma * d) into smem tile ----
    #pragma unroll
    for (int i = 0; i < TM; i++) {
        const float xq = xsq[ra + i];
        #pragma unroll
        for (int j = 0; j < TN; j++) {
            const int col = ca + j;
            const float dv = xq + wsq[col] - 2.0f * acc[i][j];
            sit[(ra + i) * SROW + col] = alp[col] * __expf(-gam[col] * dv);
        }
    }
    __syncthreads();

    // ---- per-row: max-normalize si, then serial Dempster combine over p ----
    if (tid < BM) {
        const float* srow = sit + tid * SROW;

        float mx = srow[0];
        #pragma unroll 8
        for (int p = 1; p < Pn; p++) mx = fmaxf(mx, srow[p]);
        const float inv = 1.0f / (mx + 1e-4f);

        float a[Cn + 1];
        {
            const float s0 = srow[0] * inv;
            float msum = 0.0f;
            #pragma unroll
            for (int c = 0; c < Cn; c++) {
                const float m2 = u_s[c * Pn + 0] * s0;
                a[c] = m2;
                msum += m2;
            }
            a[Cn] = 1.0f - msum;     // omega = 1 - sum_c(u*si), matching reference
        }

        for (int p = 1; p < Pn; p++) {
            const float sp = srow[p] * inv;
            const float o1 = a[Cn];
            float m2[Cn];
            float msum = 0.0f;
            #pragma unroll
            for (int c = 0; c < Cn; c++) {
                m2[c] = u_s[c * Pn + p] * sp;
                msum += m2[c];
            }
            const float o2 = 1.0f - msum;
            float sum = 0.0f;
            #pragma unroll
            for (int c = 0; c < Cn; c++) {
                const float cc = a[c] * m2[c] + a[c] * o2 + o1 * m2[c];
                a[c] = cc;
                sum += cc;
            }
            const float com = 3.0f * o1 * o2;   // reference applies same formula to omega slot
            sum += com;
            const float rr = __fdividef(1.0f, sum);
            #pragma unroll
            for (int c = 0; c < Cn; c++) a[c] *= rr;
            a[Cn] = com * rr;
        }

        float sum = 0.0f;
        #pragma unroll
        for (int c = 0; c <= Cn; c++) sum += a[c];
        const float rr = __fdividef(1.0f, sum);
        float* orow = out + (size_t)(row0 + tid) * (Cn + 1);
        #pragma unroll
        for (int c = 0; c <= Cn; c++) orow[c] = a[c] * rr;
    }
}

extern "C" void kernel_launch(void* const* d_in, const int* in_sizes, int n_in,
                              void* d_out, int out_size)
{
    const float* x    = (const float*)d_in[0];
    const float* w    = (const float*)d_in[1];
    const float* eta  = (const float*)d_in[2];
    const float* xi   = (const float*)d_in[3];
    const float* beta = (const float*)d_in[4];
    float* out = (float*)d_out;

    const size_t smem_floats =
        2 * KT * BM          // xs
        + 2 * KT * BM        // wsm
        + (size_t)BM * SROW  // sit
        + BM                 // xsq
        + Pn                 // wsq
        + Cn * Pn            // u
        + Pn                 // alpha
        + Pn;                // gamma
    const size_t smem_bytes = smem_floats * sizeof(float);

    cudaFuncSetAttribute(ds_kernel, cudaFuncAttributeMaxDynamicSharedMemorySize,
                         (int)smem_bytes);

    ds_kernel<<<Bn / BM, NT, smem_bytes>>>(x, w, eta, xi, beta, out);
}

// round 2
// speedup vs baseline: 1.8216x; 1.8216x over previous
#include <cuda_runtime.h>
#include <cstdint>

// Problem constants
#define Bn 16384
#define Fn 512
#define Pn 128
#define Cn 10

// Tiling
#define BM 128          // rows per block
#define BK 32           // K tile
#define NT 256          // threads per block
#define ASTRIDE 36      // smem row stride (floats): (36 mod 32)=4 -> conflict-free frags
#define ABUF (BM * ASTRIDE)   // 4608 words per buffer
#define SROW 129        // padded si row stride

__device__ __forceinline__ uint32_t f2tf32(float f) {
    uint32_t u;
    asm("cvt.rna.tf32.f32 %0, %1;" : "=r"(u) : "f"(f));
    return u;
}

#define MMA_TF32(cc, aa, bb)                                                     \
    asm volatile(                                                                \
        "mma.sync.aligned.m16n8k8.row.col.f32.tf32.tf32.f32 "                    \
        "{%0,%1,%2,%3},{%4,%5,%6,%7},{%8,%9},{%0,%1,%2,%3};"                     \
        : "+f"((cc)[0]), "+f"((cc)[1]), "+f"((cc)[2]), "+f"((cc)[3])             \
        : "r"((aa)[0]), "r"((aa)[1]), "r"((aa)[2]), "r"((aa)[3]),                \
          "r"((bb)[0]), "r"((bb)[1]))

__global__ __launch_bounds__(NT, 1)
void ds_kernel(const float* __restrict__ x, const float* __restrict__ w,
               const float* __restrict__ eta, const float* __restrict__ xi,
               const float* __restrict__ beta, float* __restrict__ out)
{
    extern __shared__ float sm[];
    uint32_t* As = (uint32_t*)sm;            // [2][BM][ASTRIDE] tf32 x tile
    uint32_t* Bs = As + 2 * ABUF;            // [2][Pn][ASTRIDE] tf32 w tile
    float* sit = (float*)(Bs + 2 * ABUF);    // [BM][SROW]
    float* xsq = sit + BM * SROW;            // [BM]
    float* wsq = xsq + BM;                   // [Pn]
    float* u_s = wsq + Pn;                   // [Cn][Pn]
    float* alp = u_s + Cn * Pn;              // [Pn]
    float* gam = alp + Pn;                   // [Pn]

    const int tid  = threadIdx.x;
    const int row0 = blockIdx.x * BM;

    // ---- per-prototype tables ----
    if (tid < Pn) {
        const int p = tid;
        float e = eta[p];
        gam[p] = e * e;
        alp[p] = 1.0f / (1.0f + __expf(-xi[p]));
        float b2[Cn];
        float bs = 0.0f;
        #pragma unroll
        for (int c = 0; c < Cn; c++) {
            float bv = beta[c * Pn + p];
            b2[c] = bv * bv;
            bs += b2[c];
        }
        float invb = 1.0f / bs;
        #pragma unroll
        for (int c = 0; c < Cn; c++) u_s[c * Pn + p] = b2[c] * invb;
        xsq[p] = 0.0f;
        wsq[p] = 0.0f;
    }

    // ---- global->smem staging: each thread owns 4 float4 of x, 4 of w per tile ----
    // idx = tid + 256*i  ->  row = tid/8 + 32*i (constant per i), q = tid%8
    const int srow_ = tid >> 3;           // 0..31
    const int q     = tid & 7;            // float4 slot within 32-float row chunk
    float4 stx[4], stw[4];
    float sxa[4] = {0.f, 0.f, 0.f, 0.f};
    float swa[4] = {0.f, 0.f, 0.f, 0.f};

    const float4* xg = (const float4*)x;  // pitch 128 float4 per row
    const float4* wg = (const float4*)w;

#define LOADT(t)                                                                  \
    do {                                                                          \
        _Pragma("unroll")                                                         \
        for (int i = 0; i < 4; i++) {                                             \
            const int r = srow_ + 32 * i;                                         \
            stx[i] = xg[(size_t)(row0 + r) * (Fn / 4) + (t) * (BK / 4) + q];      \
            stw[i] = wg[(size_t)r * (Fn / 4) + (t) * (BK / 4) + q];               \
        }                                                                         \
    } while (0)

#define STASH(bufv)                                                               \
    do {                                                                          \
        uint32_t* Ab = As + (bufv) * ABUF;                                        \
        uint32_t* Bb = Bs + (bufv) * ABUF;                                        \
        _Pragma("unroll")                                                         \
        for (int i = 0; i < 4; i++) {                                             \
            const int r = srow_ + 32 * i;                                         \
            float4 v = stx[i];                                                    \
            sxa[i] += v.x * v.x + v.y * v.y + v.z * v.z + v.w * v.w;              \
            uint4 tv = make_uint4(f2tf32(v.x), f2tf32(v.y), f2tf32(v.z), f2tf32(v.w)); \
            *(uint4*)&Ab[r * ASTRIDE + q * 4] = tv;                               \
            v = stw[i];                                                           \
            swa[i] += v.x * v.x + v.y * v.y + v.z * v.z + v.w * v.w;              \
            tv = make_uint4(f2tf32(v.x), f2tf32(v.y), f2tf32(v.z), f2tf32(v.w));  \
            *(uint4*)&Bb[r * ASTRIDE + q * 4] = tv;                               \
        }                                                                         \
    } while (0)

    LOADT(0);
    STASH(0);
    __syncthreads();

    // ---- warp/mma layout: 8 warps = 2(M) x 4(N); warp tile 64x32 ----
    const int warp  = tid >> 5;
    const int lane  = tid & 31;
    const int lr    = lane >> 2;          // 0..7
    const int lc    = lane & 3;           // 0..3
    const int m0    = (warp & 1) * 64;    // warp M base
    const int n0    = (warp >> 1) * 32;   // warp N base

    int aBase[4], bBase[4];
    #pragma unroll
    for (int mi = 0; mi < 4; mi++) aBase[mi] = (m0 + mi * 16 + lr) * ASTRIDE + lc;
    #pragma unroll
    for (int nj = 0; nj < 4; nj++) bBase[nj] = (n0 + nj * 8 + lr) * ASTRIDE + lc;

    float acc[4][4][4];
    #pragma unroll
    for (int mi = 0; mi < 4; mi++)
        #pragma unroll
        for (int nj = 0; nj < 4; nj++)
            #pragma unroll
            for (int e = 0; e < 4; e++) acc[mi][nj][e] = 0.0f;

    const int NTILE = Fn / BK;            // 16
    for (int t = 0; t < NTILE; t++) {
        const int buf = t & 1;
        const bool more = (t + 1 < NTILE);
        if (more) LOADT(t + 1);

        const uint32_t* Au = As + buf * ABUF;
        const uint32_t* Bu = Bs + buf * ABUF;
        #pragma unroll
        for (int k8 = 0; k8 < BK / 8; k8++) {
            const int k0 = k8 * 8;
            uint32_t a[4][4], b[4][2];
            #pragma unroll
            for (int mi = 0; mi < 4; mi++) {
                a[mi][0] = Au[aBase[mi] + k0];
                a[mi][1] = Au[aBase[mi] + 8 * ASTRIDE + k0];
                a[mi][2] = Au[aBase[mi] + k0 + 4];
                a[mi][3] = Au[aBase[mi] + 8 * ASTRIDE + k0 + 4];
            }
            #pragma unroll
            for (int nj = 0; nj < 4; nj++) {
                b[nj][0] = Bu[bBase[nj] + k0];
                b[nj][1] = Bu[bBase[nj] + k0 + 4];
            }
            #pragma unroll
            for (int mi = 0; mi < 4; mi++)
                #pragma unroll
                for (int nj = 0; nj < 4; nj++)
                    MMA_TF32(acc[mi][nj], a[mi], b[nj]);
        }
        if (more) STASH(buf ^ 1);
        __syncthreads();
    }

    // ---- finalize sum-of-squares ----
    #pragma unroll
    for (int i = 0; i < 4; i++) {
        atomicAdd(&xsq[srow_ + 32 * i], sxa[i]);
        atomicAdd(&wsq[srow_ + 32 * i], swa[i]);
    }
    __syncthreads();

    // ---- epilogue: si = alpha * exp(-gamma * d) into smem ----
    #pragma unroll
    for (int mi = 0; mi < 4; mi++) {
        const int r0_ = m0 + mi * 16 + lr;
        const int r1_ = r0_ + 8;
        const float xq0 = xsq[r0_];
        const float xq1 = xsq[r1_];
        #pragma unroll
        for (int nj = 0; nj < 4; nj++) {
            const int c0 = n0 + nj * 8 + 2 * lc;
            const int c1 = c0 + 1;
            const float wq0 = wsq[c0], wq1 = wsq[c1];
            float d00 = xq0 + wq0 - 2.0f * acc[mi][nj][0];
            float d01 = xq0 + wq1 - 2.0f * acc[mi][nj][1];
            float d10 = xq1 + wq0 - 2.0f * acc[mi][nj][2];
            float d11 = xq1 + wq1 - 2.0f * acc[mi][nj][3];
            sit[r0_ * SROW + c0] = alp[c0] * __expf(-gam[c0] * d00);
            sit[r0_ * SROW + c1] = alp[c1] * __expf(-gam[c1] * d01);
            sit[r1_ * SROW + c0] = alp[c0] * __expf(-gam[c0] * d10);
            sit[r1_ * SROW + c1] = alp[c1] * __expf(-gam[c1] * d11);
        }
    }
    __syncthreads();

    // ---- per-row: max-normalize si, then serial Dempster combine over p ----
    if (tid < BM) {
        const float* srow = sit + tid * SROW;

        float mx = srow[0];
        #pragma unroll 8
        for (int p = 1; p < Pn; p++) mx = fmaxf(mx, srow[p]);
        const float inv = 1.0f / (mx + 1e-4f);

        float a[Cn + 1];
        {
            const float s0 = srow[0] * inv;
            float msum = 0.0f;
            #pragma unroll
            for (int c = 0; c < Cn; c++) {
                const float m2 = u_s[c * Pn + 0] * s0;
                a[c] = m2;
                msum += m2;
            }
            a[Cn] = 1.0f - msum;
        }

        for (int p = 1; p < Pn; p++) {
            const float sp = srow[p] * inv;
            const float o1 = a[Cn];
            float m2[Cn];
            float msum = 0.0f;
            #pragma unroll
            for (int c = 0; c < Cn; c++) {
                m2[c] = u_s[c * Pn + p] * sp;
                msum += m2[c];
            }
            const float o2 = 1.0f - msum;
            float sum = 0.0f;
            #pragma unroll
            for (int c = 0; c < Cn; c++) {
                const float cc = a[c] * m2[c] + a[c] * o2 + o1 * m2[c];
                a[c] = cc;
                sum += cc;
            }
            const float com = 3.0f * o1 * o2;
            sum += com;
            const float rr = __fdividef(1.0f, sum);
            #pragma unroll
            for (int c = 0; c < Cn; c++) a[c] *= rr;
            a[Cn] = com * rr;
        }

        float sum = 0.0f;
        #pragma unroll
        for (int c = 0; c <= Cn; c++) sum += a[c];
        const float rr = __fdividef(1.0f, sum);
        float* orow = out + (size_t)(row0 + tid) * (Cn + 1);
        #pragma unroll
        for (int c = 0; c <= Cn; c++) orow[c] = a[c] * rr;
    }
}

extern "C" void kernel_launch(void* const* d_in, const int* in_sizes, int n_in,
                              void* d_out, int out_size)
{
    const float* x    = (const float*)d_in[0];
    const float* w    = (const float*)d_in[1];
    const float* eta  = (const float*)d_in[2];
    const float* xi   = (const float*)d_in[3];
    const float* beta = (const float*)d_in[4];
    float* out = (float*)d_out;

    const size_t smem_bytes =
        (2 * ABUF + 2 * ABUF) * sizeof(uint32_t)   // As + Bs
        + (size_t)BM * SROW * sizeof(float)        // sit
        + BM * sizeof(float)                       // xsq
        + Pn * sizeof(float)                       // wsq
        + Cn * Pn * sizeof(float)                  // u
        + Pn * sizeof(float)                       // alpha
        + Pn * sizeof(float);                      // gamma

    cudaFuncSetAttribute(ds_kernel, cudaFuncAttributeMaxDynamicSharedMemorySize,
                         (int)smem_bytes);

    ds_kernel<<<Bn / BM, NT, smem_bytes>>>(x, w, eta, xi, beta, out);
}

// round 3
// speedup vs baseline: 1.8242x; 1.0014x over previous
#include <cuda_runtime.h>
#include <cstdint>

// Problem constants
#define Bn 16384
#define Fn 512
#define Pn 128
#define Cn 10

// Tiling
#define BM 64                 // rows per block
#define BK 32                 // K tile
#define NT 256                // threads
#define NTILE (Fn / BK)       // 16
#define AST 36                // smem words per 32-float row (pad 4 -> conflict-free)
#define A_STAGE_B (BM * AST * 4)    // 9216 bytes per A stage
#define B_STAGE_B (Pn * AST * 4)    // 18432 bytes per B stage
#define OFF_AS 0
#define OFF_BS (2 * A_STAGE_B)              // 18432
#define OFF_TAIL (OFF_BS + 2 * B_STAGE_B)   // 55296
#define SROW 129
#define SMEM_BYTES (OFF_TAIL + (BM + Pn + Cn * Pn + Pn + Pn) * 4)   // 62208

__device__ __forceinline__ uint32_t cvta_s(const void* p) {
    return (uint32_t)__cvta_generic_to_shared(p);
}
__device__ __forceinline__ void cp16(uint32_t dst, const void* src) {
    asm volatile("cp.async.ca.shared.global [%0], [%1], 16;" :: "r"(dst), "l"(src));
}
__device__ __forceinline__ void ldsm4(uint32_t (&r)[4], uint32_t addr) {
    asm volatile("ldmatrix.sync.aligned.m8n8.x4.shared.b16 {%0,%1,%2,%3}, [%4];"
        : "=r"(r[0]), "=r"(r[1]), "=r"(r[2]), "=r"(r[3]) : "r"(addr));
}
#define MMA_TF32(cc, a0, a1, a2, a3, b0, b1)                                     \
    asm volatile(                                                                \
        "mma.sync.aligned.m16n8k8.row.col.f32.tf32.tf32.f32 "                    \
        "{%0,%1,%2,%3},{%4,%5,%6,%7},{%8,%9},{%0,%1,%2,%3};"                     \
        : "+f"((cc)[0]), "+f"((cc)[1]), "+f"((cc)[2]), "+f"((cc)[3])             \
        : "r"(a0), "r"(a1), "r"(a2), "r"(a3), "r"(b0), "r"(b1))

__global__ __launch_bounds__(NT, 2)
void ds_kernel(const float* __restrict__ x, const float* __restrict__ w,
               const float* __restrict__ eta, const float* __restrict__ xi,
               const float* __restrict__ beta, float* __restrict__ out)
{
    extern __shared__ char smem[];
    float* sit = (float*)smem;                      // aliases A/B stages after GEMM
    float* xsq = (float*)(smem + OFF_TAIL);         // [BM]
    float* wsq = xsq + BM;                          // [Pn]
    float* u_s = wsq + Pn;                          // [Cn][Pn]
    float* alp = u_s + Cn * Pn;                     // [Pn]
    float* gam = alp + Pn;                          // [Pn]

    const int tid  = threadIdx.x;
    const int row0 = blockIdx.x * BM;
    const uint32_t sbase = cvta_s(smem);

    // ---- async copy mapping: 6x 16B per thread per tile (2 A, 4 B) ----
    const int r8 = tid >> 3;      // 0..31
    const int q8 = tid & 7;
    const float4* xg = (const float4*)x;   // 128 float4 per row
    const float4* wg = (const float4*)w;

#define COPY(t, stg)                                                              \
    do {                                                                          \
        uint32_t ad = sbase + OFF_AS + (stg) * A_STAGE_B + r8 * 144 + q8 * 16;    \
        uint32_t bd = sbase + OFF_BS + (stg) * B_STAGE_B + r8 * 144 + q8 * 16;    \
        const float4* xs_ = xg + (size_t)(row0 + r8) * 128 + (t) * 8 + q8;        \
        const float4* ws_ = wg + (size_t)r8 * 128 + (t) * 8 + q8;                 \
        cp16(ad, xs_);                                                            \
        cp16(ad + 32 * 144, xs_ + (size_t)32 * 128);                              \
        cp16(bd, ws_);                                                            \
        cp16(bd + 32 * 144, ws_ + (size_t)32 * 128);                              \
        cp16(bd + 64 * 144, ws_ + (size_t)64 * 128);                              \
        cp16(bd + 96 * 144, ws_ + (size_t)96 * 128);                              \
        asm volatile("cp.async.commit_group;" ::: "memory");                      \
    } while (0)

    COPY(0, 0);
    COPY(1, 1);

    // ---- per-prototype tables (overlaps with cp.async of first tiles) ----
    if (tid < Pn) {
        const int p = tid;
        float e = eta[p];
        gam[p] = e * e;
        alp[p] = 1.0f / (1.0f + __expf(-xi[p]));
        float b2[Cn];
        float bs = 0.0f;
        #pragma unroll
        for (int c = 0; c < Cn; c++) {
            float bv = beta[c * Pn + p];
            b2[c] = bv * bv;
            bs += b2[c];
        }
        float invb = 1.0f / bs;
        #pragma unroll
        for (int c = 0; c < Cn; c++) u_s[c * Pn + p] = b2[c] * invb;
    }

    // ---- fragment / ldmatrix addresses ----
    const int warp = tid >> 5, lane = tid & 31;
    const int m0 = (warp & 1) * 32;            // warp M base (0/32)
    const int n0 = (warp >> 1) * 32;           // warp N base (0/32/64/96)
    const int lr = lane >> 2, lc = lane & 3;

    // A (mi tile = 16 rows): lanes 0-7 rows+0(klo), 8-15 rows+8(klo), 16-23 rows+0(khi), 24-31 rows+8(khi)
    const uint32_t aAddr0 = sbase + OFF_AS + (m0 + (lane & 15)) * 144 + ((lane & 16) ? 16 : 0);
    const uint32_t aAddr1 = aAddr0 + 16 * 144;
    // B (x4 covers nj,nj+1): lanes 0-7 nj(klo), 8-15 nj(khi), 16-23 nj+1(klo), 24-31 nj+1(khi)
    const uint32_t bAddr0 = sbase + OFF_BS + (n0 + ((lane >> 4) & 1) * 8 + (lane & 7)) * 144
                                           + ((lane & 8) ? 16 : 0);
    const uint32_t bAddr1 = bAddr0 + 16 * 144;

    // sumsq readback addresses (raw fp32 bits preserved by cp.async)
    const uint32_t xqOff = OFF_AS + (tid >> 2) * 144 + (tid & 3) * 32;  // 8 floats of row tid>>2
    const uint32_t wqOff = OFF_BS + (tid >> 1) * 144 + (tid & 1) * 64;  // 16 floats of row tid>>1

    float acc[2][4][4];
    #pragma unroll
    for (int mi = 0; mi < 2; mi++)
        #pragma unroll
        for (int nj = 0; nj < 4; nj++)
            #pragma unroll
            for (int e = 0; e < 4; e++) acc[mi][nj][e] = 0.0f;

    float xacc = 0.0f, wacc = 0.0f;

    for (int t = 0; t < NTILE; t++) {
        const int stg = t & 1;
        if (t < NTILE - 1) asm volatile("cp.async.wait_group 1;" ::: "memory");
        else               asm volatile("cp.async.wait_group 0;" ::: "memory");
        __syncthreads();

        // sumsq partial accumulation from exact fp32 bits in smem
        {
            const char* ab = smem + stg * A_STAGE_B;
            float4 v = *(const float4*)(ab + xqOff);
            xacc += v.x * v.x + v.y * v.y + v.z * v.z + v.w * v.w;
            v = *(const float4*)(ab + xqOff + 16);
            xacc += v.x * v.x + v.y * v.y + v.z * v.z + v.w * v.w;
            const char* bb = smem + stg * B_STAGE_B;
            #pragma unroll
            for (int kk = 0; kk < 4; kk++) {
                v = *(const float4*)(bb + wqOff + kk * 16);
                wacc += v.x * v.x + v.y * v.y + v.z * v.z + v.w * v.w;
            }
        }

        const uint32_t aOff = stg * A_STAGE_B;
        const uint32_t bOff = stg * B_STAGE_B;
        #pragma unroll
        for (int k8 = 0; k8 < 4; k8++) {
            uint32_t a0r[4], a1r[4], b0r[4], b1r[4];
            ldsm4(a0r, aAddr0 + aOff + k8 * 32);
            ldsm4(a1r, aAddr1 + aOff + k8 * 32);
            ldsm4(b0r, bAddr0 + bOff + k8 * 32);   // nj=0,1
            ldsm4(b1r, bAddr1 + bOff + k8 * 32);   // nj=2,3
            MMA_TF32(acc[0][0], a0r[0], a0r[1], a0r[2], a0r[3], b0r[0], b0r[1]);
            MMA_TF32(acc[0][1], a0r[0], a0r[1], a0r[2], a0r[3], b0r[2], b0r[3]);
            MMA_TF32(acc[0][2], a0r[0], a0r[1], a0r[2], a0r[3], b1r[0], b1r[1]);
            MMA_TF32(acc[0][3], a0r[0], a0r[1], a0r[2], a0r[3], b1r[2], b1r[3]);
            MMA_TF32(acc[1][0], a1r[0], a1r[1], a1r[2], a1r[3], b0r[0], b0r[1]);
            MMA_TF32(acc[1][1], a1r[0], a1r[1], a1r[2], a1r[3], b0r[2], b0r[3]);
            MMA_TF32(acc[1][2], a1r[0], a1r[1], a1r[2], a1r[3], b1r[0], b1r[1]);
            MMA_TF32(acc[1][3], a1r[0], a1r[1], a1r[2], a1r[3], b1r[2], b1r[3]);
        }
        __syncthreads();                      // all reads of stage stg done
        if (t + 2 < NTILE) COPY(t + 2, stg);  // reuse stage for tile t+2
    }

    // ---- reduce sumsq ----
    {
        float v = xacc;
        v += __shfl_xor_sync(0xffffffffu, v, 1);
        v += __shfl_xor_sync(0xffffffffu, v, 2);
        if ((tid & 3) == 0) xsq[tid >> 2] = v;
        float u = wacc;
        u += __shfl_xor_sync(0xffffffffu, u, 1);
        if ((tid & 1) == 0) wsq[tid >> 1] = u;
    }
    __syncthreads();

    // ---- epilogue: si = alpha * exp(-gamma * d) into smem (aliases A/B stages) ----
    #pragma unroll
    for (int mi = 0; mi < 2; mi++) {
        const int r0_ = m0 + mi * 16 + lr;
        const int r1_ = r0_ + 8;
        const float xq0 = xsq[r0_];
        const float xq1 = xsq[r1_];
        #pragma unroll
        for (int nj = 0; nj < 4; nj++) {
            const int c0 = n0 + nj * 8 + 2 * lc;
            const int c1 = c0 + 1;
            const float wq0 = wsq[c0], wq1 = wsq[c1];
            float d00 = xq0 + wq0 - 2.0f * acc[mi][nj][0];
            float d01 = xq0 + wq1 - 2.0f * acc[mi][nj][1];
            float d10 = xq1 + wq0 - 2.0f * acc[mi][nj][2];
            float d11 = xq1 + wq1 - 2.0f * acc[mi][nj][3];
            sit[r0_ * SROW + c0] = alp[c0] * __expf(-gam[c0] * d00);
            sit[r0_ * SROW + c1] = alp[c1] * __expf(-gam[c1] * d01);
            sit[r1_ * SROW + c0] = alp[c0] * __expf(-gam[c0] * d10);
            sit[r1_ * SROW + c1] = alp[c1] * __expf(-gam[c1] * d11);
        }
    }
    __syncthreads();

    // ---- per-row: max-normalize si, serial Dempster combine ----
    if (tid < BM) {
        const float* srow = sit + tid * SROW;

        float mx = srow[0];
        #pragma unroll 8
        for (int p = 1; p < Pn; p++) mx = fmaxf(mx, srow[p]);
        const float inv = 1.0f / (mx + 1e-4f);

        float a[Cn + 1];
        {
            const float s0 = srow[0] * inv;
            float msum = 0.0f;
            #pragma unroll
            for (int c = 0; c < Cn; c++) {
                const float m2 = u_s[c * Pn + 0] * s0;
                a[c] = m2;
                msum += m2;
            }
            a[Cn] = 1.0f - msum;
        }

        for (int p = 1; p < Pn; p++) {
            const float sp = srow[p] * inv;
            const float o1 = a[Cn];
            float m2[Cn];
            float msum = 0.0f;
            #pragma unroll
            for (int c = 0; c < Cn; c++) {
                m2[c] = u_s[c * Pn + p] * sp;
                msum += m2[c];
            }
            const float o2 = 1.0f - msum;
            float sum = 0.0f;
            #pragma unroll
            for (int c = 0; c < Cn; c++) {
                const float cc = a[c] * m2[c] + a[c] * o2 + o1 * m2[c];
                a[c] = cc;
                sum += cc;
            }
            const float com = 3.0f * o1 * o2;
            sum += com;
            const float rr = __fdividef(1.0f, sum);
            #pragma unroll
            for (int c = 0; c < Cn; c++) a[c] *= rr;
            a[Cn] = com * rr;
        }

        float sum = 0.0f;
        #pragma unroll
        for (int c = 0; c <= Cn; c++) sum += a[c];
        const float rr = __fdividef(1.0f, sum);
        float* orow = out + (size_t)(row0 + tid) * (Cn + 1);
        #pragma unroll
        for (int c = 0; c <= Cn; c++) orow[c] = a[c] * rr;
    }
}

extern "C" void kernel_launch(void* const* d_in, const int* in_sizes, int n_in,
                              void* d_out, int out_size)
{
    const float* x    = (const float*)d_in[0];
    const float* w    = (const float*)d_in[1];
    const float* eta  = (const float*)d_in[2];
    const float* xi   = (const float*)d_in[3];
    const float* beta = (const float*)d_in[4];
    float* out = (float*)d_out;

    cudaFuncSetAttribute(ds_kernel, cudaFuncAttributeMaxDynamicSharedMemorySize,
                         SMEM_BYTES);

    ds_kernel<<<Bn / BM, NT, SMEM_BYTES>>>(x, w, eta, xi, beta, out);
}

// round 5
// speedup vs baseline: 2.4966x; 1.3686x over previous
#include <cuda_runtime.h>
#include <cstdint>

// Problem constants
#define Bn 16384
#define Fn 512
#define Pn 128
#define Cn 10

// Tiling
#define BM 64                 // rows per block
#define BK 32                 // K tile
#define NT 256                // threads
#define NTILE (Fn / BK)       // 16
#define NSTG 3                // cp.async stages
#define STG_B 27648           // bytes per stage: A(64x144) + B(128x144)
#define B_OFF 9216            // B offset within a stage
#define OFF_TAIL (NSTG * STG_B)   // 82944
#define SROW 132              // si row stride (words): 16B-aligned rows, bank shift 4
#define UW 16                 // u_t row stride (words)
// tail floats: xsq 64 + wsq 128 + u_t 128*16 + alp 128 + gam 128
#define SMEM_BYTES (OFF_TAIL + (64 + 128 + 128 * UW + 128 + 128) * 4)

__device__ __forceinline__ uint32_t cvta_s(const void* p) {
    return (uint32_t)__cvta_generic_to_shared(p);
}
__device__ __forceinline__ void cp16(uint32_t dst, const void* src) {
    asm volatile("cp.async.ca.shared.global [%0], [%1], 16;" :: "r"(dst), "l"(src));
}
template <int N>
__device__ __forceinline__ void cp_wait() {
    asm volatile("cp.async.wait_group %0;" :: "n"(N) : "memory");
}
__device__ __forceinline__ void ldsm4(uint32_t (&r)[4], uint32_t addr) {
    asm volatile("ldmatrix.sync.aligned.m8n8.x4.shared.b16 {%0,%1,%2,%3}, [%4];"
        : "=r"(r[0]), "=r"(r[1]), "=r"(r[2]), "=r"(r[3]) : "r"(addr));
}
#define MMA_TF32(cc, a0, a1, a2, a3, b0, b1)                                     \
    asm volatile(                                                                \
        "mma.sync.aligned.m16n8k8.row.col.f32.tf32.tf32.f32 "                    \
        "{%0,%1,%2,%3},{%4,%5,%6,%7},{%8,%9},{%0,%1,%2,%3};"                     \
        : "+f"((cc)[0]), "+f"((cc)[1]), "+f"((cc)[2]), "+f"((cc)[3])             \
        : "r"(a0), "r"(a1), "r"(a2), "r"(a3), "r"(b0), "r"(b1))

__global__ __launch_bounds__(NT, 2)
void ds_kernel(const float* __restrict__ x, const float* __restrict__ w,
               const float* __restrict__ eta, const float* __restrict__ xi,
               const float* __restrict__ beta, float* __restrict__ out)
{
    extern __shared__ char smem[];
    float* sit = (float*)smem;                      // [BM][SROW], aliases stages post-GEMM
    float* xsq = (float*)(smem + OFF_TAIL);         // [64]
    float* wsq = xsq + 64;                          // [128]
    float* u_t = wsq + 128;                         // [128][UW]
    float* alp = u_t + 128 * UW;                    // [128]
    float* gam = alp + 128;                         // [128]

    const int tid  = threadIdx.x;
    const int row0 = blockIdx.x * BM;
    const uint32_t sbase = cvta_s(smem);

    // ---- async copy mapping: 6x16B per thread per tile (2 A rows, 4 B rows) ----
    const int r8 = tid >> 3;      // 0..31
    const int q8 = tid & 7;
    const float4* xg = (const float4*)x;   // 128 float4 per row
    const float4* wg = (const float4*)w;

#define COPY(t, stg)                                                              \
    do {                                                                          \
        uint32_t ad = sbase + (stg) * STG_B + r8 * 144 + q8 * 16;                 \
        uint32_t bd = ad + B_OFF;                                                 \
        const float4* xs_ = xg + (size_t)(row0 + r8) * 128 + (t) * 8 + q8;        \
        const float4* ws_ = wg + (size_t)r8 * 128 + (t) * 8 + q8;                 \
        cp16(ad, xs_);                                                            \
        cp16(ad + 32 * 144, xs_ + (size_t)32 * 128);                              \
        cp16(bd, ws_);                                                            \
        cp16(bd + 32 * 144, ws_ + (size_t)32 * 128);                              \
        cp16(bd + 64 * 144, ws_ + (size_t)64 * 128);                              \
        cp16(bd + 96 * 144, ws_ + (size_t)96 * 128);                              \
        asm volatile("cp.async.commit_group;" ::: "memory");                      \
    } while (0)

    COPY(0, 0);
    COPY(1, 1);

    // ---- per-prototype tables (overlapped with first copies) ----
    if (tid < Pn) {
        const int p = tid;
        float e = eta[p];
        gam[p] = e * e;
        alp[p] = 1.0f / (1.0f + __expf(-xi[p]));
        float b2[Cn];
        float bs = 0.0f;
        #pragma unroll
        for (int c = 0; c < Cn; c++) {
            float bv = beta[c * Pn + p];
            b2[c] = bv * bv;
            bs += b2[c];
        }
        float invb = 1.0f / bs;
        // layout: classes 3g+k at slot g*4+k (g<3); class 9 at slot 12; rest 0
        #pragma unroll
        for (int s = 0; s < UW; s++) u_t[p * UW + s] = 0.0f;
        #pragma unroll
        for (int c = 0; c < Cn; c++) {
            const int slot = (c < 9) ? (c / 3) * 4 + (c % 3) : 12;
            u_t[p * UW + slot] = b2[c] * invb;
        }
    }

    // ---- fragment addresses (verified layout from R3) ----
    const int warp = tid >> 5, lane = tid & 31;
    const int m0 = (warp & 1) * 32;            // warp M base
    const int n0 = (warp >> 1) * 32;           // warp N base
    const int lr = lane >> 2, lc = lane & 3;

    const uint32_t aAddr0 = sbase + (m0 + (lane & 15)) * 144 + ((lane & 16) ? 16 : 0);
    const uint32_t aAddr1 = aAddr0 + 16 * 144;
    const uint32_t bAddr0 = sbase + B_OFF + (n0 + ((lane >> 4) & 1) * 8 + (lane & 7)) * 144
                                          + ((lane & 8) ? 16 : 0);
    const uint32_t bAddr1 = bAddr0 + 16 * 144;

    // sumsq readback offsets within a stage (raw fp32 bits preserved by cp.async)
    const uint32_t xqOff = (tid >> 2) * 144 + (tid & 3) * 32;
    const uint32_t wqOff = B_OFF + (tid >> 1) * 144 + (tid & 1) * 64;

    float acc[2][4][4];
    #pragma unroll
    for (int mi = 0; mi < 2; mi++)
        #pragma unroll
        for (int nj = 0; nj < 4; nj++)
            #pragma unroll
            for (int e = 0; e < 4; e++) acc[mi][nj][e] = 0.0f;

    float xacc = 0.0f, wacc = 0.0f;

    for (int t = 0; t < NTILE; t++) {
        const int stg = t % NSTG;
        if (t < NTILE - 1) cp_wait<1>();
        else               cp_wait<0>();
        __syncthreads();
        // safe now: all warps finished compute of t-1, whose stage (t+2)%3 we refill
        if (t + 2 < NTILE) COPY(t + 2, (t + 2) % NSTG);

        // sumsq partials from exact fp32 bits
        {
            const char* sb = smem + stg * STG_B;
            float4 v = *(const float4*)(sb + xqOff);
            xacc += v.x * v.x + v.y * v.y + v.z * v.z + v.w * v.w;
            v = *(const float4*)(sb + xqOff + 16);
            xacc += v.x * v.x + v.y * v.y + v.z * v.z + v.w * v.w;
            #pragma unroll
            for (int kk = 0; kk < 4; kk++) {
                v = *(const float4*)(sb + wqOff + kk * 16);
                wacc += v.x * v.x + v.y * v.y + v.z * v.z + v.w * v.w;
            }
        }

        const uint32_t so = stg * STG_B;
        #pragma unroll
        for (int k8 = 0; k8 < 4; k8++) {
            uint32_t a0r[4], a1r[4], b0r[4], b1r[4];
            ldsm4(a0r, aAddr0 + so + k8 * 32);
            ldsm4(a1r, aAddr1 + so + k8 * 32);
            ldsm4(b0r, bAddr0 + so + k8 * 32);
            ldsm4(b1r, bAddr1 + so + k8 * 32);
            MMA_TF32(acc[0][0], a0r[0], a0r[1], a0r[2], a0r[3], b0r[0], b0r[1]);
            MMA_TF32(acc[0][1], a0r[0], a0r[1], a0r[2], a0r[3], b0r[2], b0r[3]);
            MMA_TF32(acc[0][2], a0r[0], a0r[1], a0r[2], a0r[3], b1r[0], b1r[1]);
            MMA_TF32(acc[0][3], a0r[0], a0r[1], a0r[2], a0r[3], b1r[2], b1r[3]);
            MMA_TF32(acc[1][0], a1r[0], a1r[1], a1r[2], a1r[3], b0r[0], b0r[1]);
            MMA_TF32(acc[1][1], a1r[0], a1r[1], a1r[2], a1r[3], b0r[2], b0r[3]);
            MMA_TF32(acc[1][2], a1r[0], a1r[1], a1r[2], a1r[3], b1r[0], b1r[1]);
            MMA_TF32(acc[1][3], a1r[0], a1r[1], a1r[2], a1r[3], b1r[2], b1r[3]);
        }
    }

    // ---- reduce sumsq ----
    {
        float v = xacc;
        v += __shfl_xor_sync(0xffffffffu, v, 1);
        v += __shfl_xor_sync(0xffffffffu, v, 2);
        if ((tid & 3) == 0) xsq[tid >> 2] = v;
        float u = wacc;
        u += __shfl_xor_sync(0xffffffffu, u, 1);
        if ((tid & 1) == 0) wsq[tid >> 1] = u;
    }
    __syncthreads();   // also fences last MMA reads before sit aliases stages

    // ---- epilogue: si = alpha * exp(-gamma * d) ----
    #pragma unroll
    for (int mi = 0; mi < 2; mi++) {
        const int r0_ = m0 + mi * 16 + lr;
        const int r1_ = r0_ + 8;
        const float xq0 = xsq[r0_];
        const float xq1 = xsq[r1_];
        #pragma unroll
        for (int nj = 0; nj < 4; nj++) {
            const int c0 = n0 + nj * 8 + 2 * lc;
            const int c1 = c0 + 1;
            const float wq0 = wsq[c0], wq1 = wsq[c1];
            float d00 = xq0 + wq0 - 2.0f * acc[mi][nj][0];
            float d01 = xq0 + wq1 - 2.0f * acc[mi][nj][1];
            float d10 = xq1 + wq0 - 2.0f * acc[mi][nj][2];
            float d11 = xq1 + wq1 - 2.0f * acc[mi][nj][3];
            sit[r0_ * SROW + c0] = alp[c0] * __expf(-gam[c0] * d00);
            sit[r0_ * SROW + c1] = alp[c1] * __expf(-gam[c1] * d01);
            sit[r1_ * SROW + c0] = alp[c0] * __expf(-gam[c0] * d10);
            sit[r1_ * SROW + c1] = alp[c1] * __expf(-gam[c1] * d11);
        }
    }
    __syncthreads();

    // ---- scan: 4 threads per row, linear s-space recurrence ----
    // s_c = a_c + omega;  step: s' = s*(u*sp + o2) + 2*omega*o2; omega' = 3*omega*o2
    // normalization is a common scale -> applied every 8 steps only.
    {
        const int row = tid >> 2;
        const int g   = tid & 3;
        const float* srow = sit + row * SROW;

        float mx = -1e30f;
        #pragma unroll
        for (int j = 0; j < 8; j++) {
            float4 v = *(const float4*)&srow[g * 32 + j * 4];
            mx = fmaxf(mx, fmaxf(fmaxf(v.x, v.y), fmaxf(v.z, v.w)));
        }
        mx = fmaxf(mx, __shfl_xor_sync(0xffffffffu, mx, 1));
        mx = fmaxf(mx, __shfl_xor_sync(0xffffffffu, mx, 2));
        const float inv = 1.0f / (mx + 1e-4f);

        float s0_, s1_, s2_, o;
        {
            const float sp = srow[0] * inv;
            const float4 u4 = *(const float4*)&u_t[0 * UW + g * 4];
            o = 1.0f - sp;
            s0_ = fmaf(u4.x, sp, o);
            s1_ = fmaf(u4.y, sp, o);
            s2_ = fmaf(u4.z, sp, o);
        }

        #pragma unroll 8
        for (int p = 1; p < Pn; p++) {
            const float sp = srow[p] * inv;
            const float4 u4 = *(const float4*)&u_t[p * UW + g * 4];
            const float o2 = 1.0f - sp;
            const float oo2 = o * o2;
            const float add = oo2 + oo2;
            s0_ = fmaf(s0_, fmaf(u4.x, sp, o2), add);
            s1_ = fmaf(s1_, fmaf(u4.y, sp, o2), add);
            s2_ = fmaf(s2_, fmaf(u4.z, sp, o2), add);
            o = 3.0f * oo2;
            if ((p & 7) == 7) {   // periodic renormalization (pure rescale)
                float part = (g == 3) ? s0_ : (s0_ + s1_ + s2_);
                part += __shfl_xor_sync(0xffffffffu, part, 1);
                part += __shfl_xor_sync(0xffffffffu, part, 2);
                const float rr = __fdividef(1.0f, part - 9.0f * o);
                s0_ *= rr; s1_ *= rr; s2_ *= rr; o *= rr;
            }
        }

        float part = (g == 3) ? s0_ : (s0_ + s1_ + s2_);
        part += __shfl_xor_sync(0xffffffffu, part, 1);
        part += __shfl_xor_sync(0xffffffffu, part, 2);
        const float rr = __fdividef(1.0f, part - 9.0f * o);

        float* orow = out + (size_t)(row0 + row) * (Cn + 1);
        if (g < 3) {
            orow[3 * g + 0] = (s0_ - o) * rr;
            orow[3 * g + 1] = (s1_ - o) * rr;
            orow[3 * g + 2] = (s2_ - o) * rr;
        } else {
            orow[9]  = (s0_ - o) * rr;
            orow[10] = o * rr;
        }
    }
}

extern "C" void kernel_launch(void* const* d_in, const int* in_sizes, int n_in,
                              void* d_out, int out_size)
{
    const float* x    = (const float*)d_in[0];
    const float* w    = (const float*)d_in[1];
    const float* eta  = (const float*)d_in[2];
    const float* xi   = (const float*)d_in[3];
    const float* beta = (const float*)d_in[4];
    float* out = (float*)d_out;

    cudaFuncSetAttribute(ds_kernel, cudaFuncAttributeMaxDynamicSharedMemorySize,
                         SMEM_BYTES);

    ds_kernel<<<Bn / BM, NT, SMEM_BYTES>>>(x, w, eta, xi, beta, out);
}